// round 3
// baseline (speedup 1.0000x reference)
#include <cuda_runtime.h>
#include <cstdint>

#define NN 100000
#define NE 1600000

// Scratch (allocation-free rule: __device__ globals)
__device__ int   g_mode;           // 0=int64, 1=int32, 2=float32 edge-index encoding
__device__ float g_deg[NN];        // degree -> dinv = rsqrt(deg)
__device__ float g_agg1[NN * 8];   // layer-1 aggregated 6-dim features (padded to 8)
__device__ float g_p[NN * 8];      // p = relu(h1) @ W2
__device__ float g_out[NN * 8];    // layer-2 accumulator (atomics stay off d_out)
__device__ int   g_src[NE];
__device__ int   g_dst[NE];

// K0: probe edge-index dtype. Reads first 1024 "int64 slots" (8KB, always in
// bounds: buffer is >= 12.8MB under every interpretation).
//  - valid int64 node ids  -> all in [0,NN)           -> mode 0
//  - float32 data as int64 -> huge values             -> not mode 0
//  - int32 data as int64   -> packed pairs >= 2^32    -> not mode 0
//  - float32 data as float -> integral, in [0,NN)     -> mode 2
//  - int32 data as float   -> denormals, non-integral -> mode 1
__global__ void k_probe(const void* ei) {
    __shared__ int ok64, okf;
    int t = threadIdx.x;
    if (t == 0) { ok64 = 1; okf = 1; }
    __syncthreads();
    const long long* p64 = (const long long*)ei;
    const float*     pf  = (const float*)ei;
    for (int i = t; i < 1024; i += blockDim.x) {
        long long v = p64[i];
        if (v < 0 || v >= NN) ok64 = 0;  // racing stores of 0: benign
        float f = pf[i];
        if (!(f >= 0.0f && f < (float)NN && f == floorf(f))) okf = 0;
    }
    __syncthreads();
    if (t == 0) g_mode = ok64 ? 0 : (okf ? 2 : 1);
}

// K1: zero agg1, init deg to 1.0 (self-loop)
__global__ void k_init(int n) {
    int i = blockIdx.x * blockDim.x + threadIdx.x;
    if (i < n * 8) g_agg1[i] = 0.0f;
    if (i < n)     g_deg[i]  = 1.0f;
}

// K2: decode edge index per detected mode, clamp bad indices to -1, degree count
__global__ void k_cvt(const void* ei, int E) {
    int e = blockIdx.x * blockDim.x + threadIdx.x;
    if (e >= E) return;
    int mode = g_mode;
    int s, d;
    if (mode == 0) {
        const long long* p = (const long long*)ei;
        s = (int)p[e]; d = (int)p[E + e];
    } else if (mode == 1) {
        const int* p = (const int*)ei;
        s = p[e]; d = p[E + e];
    } else {
        const float* p = (const float*)ei;
        s = (int)p[e]; d = (int)p[E + e];
    }
    if ((unsigned)s >= NN) s = -1;
    if ((unsigned)d >= NN) d = -1;
    g_src[e] = s;
    g_dst[e] = d;
    if (d >= 0) atomicAdd(&g_deg[d], 1.0f);
}

// K3: dinv = rsqrt(deg)
__global__ void k_rsqrt(int n) {
    int v = blockIdx.x * blockDim.x + threadIdx.x;
    if (v < n) g_deg[v] = rsqrtf(g_deg[v]);
}

// K4: layer-1 edge scatter of raw 6-dim x (pre-GEMM aggregation)
__global__ void k_scat1(const float* __restrict__ x, int E) {
    int e = blockIdx.x * blockDim.x + threadIdx.x;
    if (e >= E) return;
    int s = g_src[e];
    int d = g_dst[e];
    if (s < 0 || d < 0) return;
    float c = g_deg[s] * g_deg[d];
    const float* xs = x + (size_t)s * 6;
    float* ag = g_agg1 + (size_t)d * 8;
#pragma unroll
    for (int i = 0; i < 6; i++) atomicAdd(ag + i, xs[i] * c);
}

// K5: per-node: finish layer-1 (+self), h=relu(a@W1+b1), p=h@W2,
//     store p, seed g_out = p*dinv^2 + b2
__global__ void k_node(const float* __restrict__ x,
                       const float* __restrict__ W1, const float* __restrict__ b1,
                       const float* __restrict__ W2, const float* __restrict__ b2,
                       int n) {
    __shared__ float sW1[6 * 64];
    __shared__ float sW2[64 * 8];
    __shared__ float sb1[64];
    __shared__ float sb2[8];
    for (int i = threadIdx.x; i < 6 * 64; i += blockDim.x) sW1[i] = W1[i];
    for (int i = threadIdx.x; i < 64 * 8; i += blockDim.x) sW2[i] = W2[i];
    for (int i = threadIdx.x; i < 64;     i += blockDim.x) sb1[i] = b1[i];
    for (int i = threadIdx.x; i < 8;      i += blockDim.x) sb2[i] = b2[i];
    __syncthreads();

    int v = blockIdx.x * blockDim.x + threadIdx.x;
    if (v >= n) return;

    float di = g_deg[v];
    float selfc = di * di;

    const float* ag = g_agg1 + (size_t)v * 8;
    const float* xv = x + (size_t)v * 6;
    float a[6];
#pragma unroll
    for (int i = 0; i < 6; i++) a[i] = ag[i] + xv[i] * selfc;

    float p[8];
#pragma unroll
    for (int k = 0; k < 8; k++) p[k] = 0.0f;

#pragma unroll 8
    for (int j = 0; j < 64; j++) {
        float h = sb1[j];
#pragma unroll
        for (int i = 0; i < 6; i++) h = fmaf(a[i], sW1[i * 64 + j], h);
        h = fmaxf(h, 0.0f);
#pragma unroll
        for (int k = 0; k < 8; k++) p[k] = fmaf(h, sW2[j * 8 + k], p[k]);
    }

    float* pr = g_p + (size_t)v * 8;
    float* o  = g_out + (size_t)v * 8;
#pragma unroll
    for (int k = 0; k < 8; k++) {
        pr[k] = p[k];
        o[k]  = p[k] * selfc + sb2[k];
    }
}

// K6: layer-2 edge scatter of 8-dim p into g_out
__global__ void k_scat2(int E) {
    int e = blockIdx.x * blockDim.x + threadIdx.x;
    if (e >= E) return;
    int s = g_src[e];
    int d = g_dst[e];
    if (s < 0 || d < 0) return;
    float c = g_deg[s] * g_deg[d];
    const float* ps = g_p + (size_t)s * 8;
    float* o = g_out + (size_t)d * 8;
#pragma unroll
    for (int k = 0; k < 8; k++) atomicAdd(o + k, ps[k] * c);
}

// K7: plain scalar copy to harness output
__global__ void k_final(float* __restrict__ out, int n8) {
    int i = blockIdx.x * blockDim.x + threadIdx.x;
    if (i < n8) out[i] = g_out[i];
}

extern "C" void kernel_launch(void* const* d_in, const int* in_sizes, int n_in,
                              void* d_out, int out_size) {
    const float* x  = (const float*)d_in[0];
    const void*  ei = d_in[1];
    const float* W1 = (const float*)d_in[2];
    const float* b1 = (const float*)d_in[3];
    const float* W2 = (const float*)d_in[4];
    const float* b2 = (const float*)d_in[5];
    float*       out = (float*)d_out;

    const int N = NN;
    const int E = NE;

    const int TB = 256;
    k_probe <<<1, 256>>>(ei);
    k_init  <<<(N * 8 + TB - 1) / TB, TB>>>(N);
    k_cvt   <<<(E + TB - 1) / TB, TB>>>(ei, E);
    k_rsqrt <<<(N + TB - 1) / TB, TB>>>(N);
    k_scat1 <<<(E + TB - 1) / TB, TB>>>(x, E);
    k_node  <<<(N + TB - 1) / TB, TB>>>(x, W1, b1, W2, b2, N);
    k_scat2 <<<(E + TB - 1) / TB, TB>>>(E);
    k_final <<<(N * 8 + TB - 1) / TB, TB>>>(out, N * 8);
}

// round 4
// speedup vs baseline: 2.3933x; 2.3933x over previous
#include <cuda_runtime.h>
#include <cstdint>

#define NN 100000
#define NE 1600000

// Scratch (allocation-free rule: __device__ globals; 256B-aligned by default)
__device__ int   g_mode;            // 0=int64, 1=int32, 2=float32 edge-index encoding
__device__ float g_deg[NN];         // degree -> dinv = rsqrt(deg)
__device__ float g_xs[NN * 8];      // xscaled = x * dinv, padded to 8 floats/row
__device__ float g_agg1[NN * 8];    // layer-1: sum of xscaled[src] per dst
__device__ float g_p[NN * 8];       // pscaled = (relu(h)@W2) * dinv
__device__ float g_out[NN * 8];     // layer-2 accumulator
__device__ int2  g_edge[NE];        // packed (src, dst)

__device__ __forceinline__ void red_add_v4(float* p, float a, float b, float c, float d) {
    asm volatile("red.global.add.v4.f32 [%0], {%1,%2,%3,%4};"
                 :: "l"(p), "f"(a), "f"(b), "f"(c), "f"(d) : "memory");
}

// K0: probe edge-index dtype (see R2 notes; each misinterpretation is detectable)
__global__ void k_probe(const void* ei) {
    __shared__ int ok64, okf;
    int t = threadIdx.x;
    if (t == 0) { ok64 = 1; okf = 1; }
    __syncthreads();
    const long long* p64 = (const long long*)ei;
    const float*     pf  = (const float*)ei;
    for (int i = t; i < 1024; i += blockDim.x) {
        long long v = p64[i];
        if (v < 0 || v >= NN) ok64 = 0;
        float f = pf[i];
        if (!(f >= 0.0f && f < (float)NN && f == floorf(f))) okf = 0;
    }
    __syncthreads();
    if (t == 0) g_mode = ok64 ? 0 : (okf ? 2 : 1);
}

// K1: zero agg1, init deg to 1.0 (self-loop)
__global__ void k_init(int n) {
    int i = blockIdx.x * blockDim.x + threadIdx.x;
    if (i < n * 8) g_agg1[i] = 0.0f;
    if (i < n)     g_deg[i]  = 1.0f;
}

// K2: decode edge index, pack int2, clamp bad indices to -1, count degree
__global__ void k_cvt(const void* ei, int E) {
    int e = blockIdx.x * blockDim.x + threadIdx.x;
    if (e >= E) return;
    int mode = g_mode;
    int s, d;
    if (mode == 0) {
        const long long* p = (const long long*)ei;
        s = (int)p[e]; d = (int)p[E + e];
    } else if (mode == 1) {
        const int* p = (const int*)ei;
        s = p[e]; d = p[E + e];
    } else {
        const float* p = (const float*)ei;
        s = (int)p[e]; d = (int)p[E + e];
    }
    if ((unsigned)s >= NN) s = -1;
    if ((unsigned)d >= NN) d = -1;
    g_edge[e] = make_int2(s, d);
    if (d >= 0) atomicAdd(&g_deg[d], 1.0f);
}

// K3: dinv = rsqrt(deg); xscaled[v] = x[v] * dinv (padded 6 -> 8)
__global__ void k_prep(const float* __restrict__ x, int n) {
    int v = blockIdx.x * blockDim.x + threadIdx.x;
    if (v >= n) return;
    float di = rsqrtf(g_deg[v]);
    g_deg[v] = di;
    const float* xv = x + (size_t)v * 6;
    float4* o = (float4*)(g_xs + (size_t)v * 8);
    o[0] = make_float4(xv[0] * di, xv[1] * di, xv[2] * di, xv[3] * di);
    o[1] = make_float4(xv[4] * di, xv[5] * di, 0.0f, 0.0f);
}

// K4: layer-1 scatter: agg1[d] += xscaled[s]   (no per-edge coefficients!)
__global__ void k_scat1(int E) {
    int e = blockIdx.x * blockDim.x + threadIdx.x;
    if (e >= E) return;
    int2 ed = g_edge[e];
    if (ed.x < 0 || ed.y < 0) return;
    const float4* xs = (const float4*)(g_xs + (size_t)ed.x * 8);
    float4 v0 = __ldg(xs);
    float4 v1 = __ldg(xs + 1);
    float* ag = g_agg1 + (size_t)ed.y * 8;
    red_add_v4(ag,     v0.x, v0.y, v0.z, v0.w);
    red_add_v4(ag + 4, v1.x, v1.y, 0.0f, 0.0f);
}

// K5: per-node: a = di*(agg1 + xscaled); h = relu(a@W1+b1); p = h@W2;
//     pscaled = p*di  -> g_p, and seed g_out with pscaled (self-loop term)
__global__ void k_node(const float* __restrict__ W1, const float* __restrict__ b1,
                       const float* __restrict__ W2, int n) {
    __shared__ float sW1[6 * 64];
    __shared__ float sW2[64 * 8];
    __shared__ float sb1[64];
    for (int i = threadIdx.x; i < 6 * 64; i += blockDim.x) sW1[i] = W1[i];
    for (int i = threadIdx.x; i < 64 * 8; i += blockDim.x) sW2[i] = W2[i];
    for (int i = threadIdx.x; i < 64;     i += blockDim.x) sb1[i] = b1[i];
    __syncthreads();

    int v = blockIdx.x * blockDim.x + threadIdx.x;
    if (v >= n) return;

    float di = g_deg[v];
    const float4* ag = (const float4*)(g_agg1 + (size_t)v * 8);
    const float4* xs = (const float4*)(g_xs + (size_t)v * 8);
    float4 a0 = ag[0], a1 = ag[1];
    float4 x0 = xs[0], x1 = xs[1];

    float a[6];
    a[0] = di * (a0.x + x0.x);
    a[1] = di * (a0.y + x0.y);
    a[2] = di * (a0.z + x0.z);
    a[3] = di * (a0.w + x0.w);
    a[4] = di * (a1.x + x1.x);
    a[5] = di * (a1.y + x1.y);

    float p[8];
#pragma unroll
    for (int k = 0; k < 8; k++) p[k] = 0.0f;

#pragma unroll 8
    for (int j = 0; j < 64; j++) {
        float h = sb1[j];
#pragma unroll
        for (int i = 0; i < 6; i++) h = fmaf(a[i], sW1[i * 64 + j], h);
        h = fmaxf(h, 0.0f);
#pragma unroll
        for (int k = 0; k < 8; k++) p[k] = fmaf(h, sW2[j * 8 + k], p[k]);
    }

    float4 q0 = make_float4(p[0] * di, p[1] * di, p[2] * di, p[3] * di);
    float4 q1 = make_float4(p[4] * di, p[5] * di, p[6] * di, p[7] * di);
    float4* pr = (float4*)(g_p + (size_t)v * 8);
    float4* o  = (float4*)(g_out + (size_t)v * 8);
    pr[0] = q0; pr[1] = q1;   // pscaled for layer-2 gather
    o[0]  = q0; o[1]  = q1;   // seeds accumulator with self term (x di at the end)
}

// K6: layer-2 scatter: g_out[d] += pscaled[s]
__global__ void k_scat2(int E) {
    int e = blockIdx.x * blockDim.x + threadIdx.x;
    if (e >= E) return;
    int2 ed = g_edge[e];
    if (ed.x < 0 || ed.y < 0) return;
    const float4* ps = (const float4*)(g_p + (size_t)ed.x * 8);
    float4 q0 = __ldg(ps);
    float4 q1 = __ldg(ps + 1);
    float* o = g_out + (size_t)ed.y * 8;
    red_add_v4(o,     q0.x, q0.y, q0.z, q0.w);
    red_add_v4(o + 4, q1.x, q1.y, q1.z, q1.w);
}

// K7: out[v] = di * accum[v] + b2  (vector stores)
__global__ void k_final(const float* __restrict__ b2, float* __restrict__ out, int n) {
    int v = blockIdx.x * blockDim.x + threadIdx.x;
    if (v >= n) return;
    float di = g_deg[v];
    float4 bb0 = make_float4(b2[0], b2[1], b2[2], b2[3]);
    float4 bb1 = make_float4(b2[4], b2[5], b2[6], b2[7]);
    const float4* a = (const float4*)(g_out + (size_t)v * 8);
    float4 v0 = a[0], v1 = a[1];
    float4* o = (float4*)(out + (size_t)v * 8);
    o[0] = make_float4(fmaf(v0.x, di, bb0.x), fmaf(v0.y, di, bb0.y),
                       fmaf(v0.z, di, bb0.z), fmaf(v0.w, di, bb0.w));
    o[1] = make_float4(fmaf(v1.x, di, bb1.x), fmaf(v1.y, di, bb1.y),
                       fmaf(v1.z, di, bb1.z), fmaf(v1.w, di, bb1.w));
}

extern "C" void kernel_launch(void* const* d_in, const int* in_sizes, int n_in,
                              void* d_out, int out_size) {
    const float* x  = (const float*)d_in[0];
    const void*  ei = d_in[1];
    const float* W1 = (const float*)d_in[2];
    const float* b1 = (const float*)d_in[3];
    const float* W2 = (const float*)d_in[4];
    const float* b2 = (const float*)d_in[5];
    float*       out = (float*)d_out;

    const int N = NN;
    const int E = NE;
    const int TB = 256;

    k_probe <<<1, 256>>>(ei);
    k_init  <<<(N * 8 + TB - 1) / TB, TB>>>(N);
    k_cvt   <<<(E + TB - 1) / TB, TB>>>(ei, E);
    k_prep  <<<(N + TB - 1) / TB, TB>>>(x, N);
    k_scat1 <<<(E + TB - 1) / TB, TB>>>(E);
    k_node  <<<(N + TB - 1) / TB, TB>>>(W1, b1, W2, N);
    k_scat2 <<<(E + TB - 1) / TB, TB>>>(E);
    k_final <<<(N + TB - 1) / TB, TB>>>(b2, out, N);
}

// round 5
// speedup vs baseline: 2.4532x; 1.0250x over previous
#include <cuda_runtime.h>
#include <cstdint>

#define NN 100000
#define NE 1600000

// Scratch (allocation-free rule: __device__ globals)
__device__ int   g_mode;            // 0=int64, 1=int32, 2=float32 edge-index encoding
__device__ float g_deg[NN];         // degree -> dinv = rsqrt(deg)
__device__ float g_xs[NN * 8];      // xscaled = x * dinv, padded to 8 floats/row
__device__ float g_agg1[NN * 8];    // layer-1: sum of xscaled[src] per dst
__device__ float g_p[NN * 8];       // pscaled = (relu(h)@W2) * dinv
__device__ float g_out[NN * 8];     // layer-2 accumulator
__device__ int2  g_edge[NE];        // packed (src, dst)

__device__ __forceinline__ void red_add_v4(float* p, float a, float b, float c, float d) {
    asm volatile("red.global.add.v4.f32 [%0], {%1,%2,%3,%4};"
                 :: "l"(p), "f"(a), "f"(b), "f"(c), "f"(d) : "memory");
}
__device__ __forceinline__ void red_add_v2(float* p, float a, float b) {
    asm volatile("red.global.add.v2.f32 [%0], {%1,%2};"
                 :: "l"(p), "f"(a), "f"(b) : "memory");
}

// K1: block 0 probes edge dtype; all blocks zero agg1 (float4) and init deg=1
__global__ void k_init(const void* ei, int n) {
    if (blockIdx.x == 0) {
        __shared__ int ok64, okf;
        int t = threadIdx.x;
        if (t == 0) { ok64 = 1; okf = 1; }
        __syncthreads();
        const long long* p64 = (const long long*)ei;
        const float*     pf  = (const float*)ei;
        for (int i = t; i < 1024; i += blockDim.x) {
            long long v = p64[i];
            if (v < 0 || v >= NN) ok64 = 0;
            float f = pf[i];
            if (!(f >= 0.0f && f < (float)NN && f == floorf(f))) okf = 0;
        }
        __syncthreads();
        if (t == 0) g_mode = ok64 ? 0 : (okf ? 2 : 1);
    }
    int i = blockIdx.x * blockDim.x + threadIdx.x;
    if (i < n * 2) ((float4*)g_agg1)[i] = make_float4(0.f, 0.f, 0.f, 0.f);
    if (i < n)     g_deg[i] = 1.0f;
}

// K2: decode 2 edges/thread, pack int4, clamp bad indices, count degree
__global__ void k_cvt(const void* ei, int E) {
    int e2 = blockIdx.x * blockDim.x + threadIdx.x;
    int e = e2 * 2;
    if (e >= E) return;
    int mode = g_mode;
    int s0, s1, d0, d1;
    if (mode == 0) {
        const longlong2* ps = (const longlong2*)ei;
        const longlong2* pd = (const longlong2*)((const long long*)ei + E);
        longlong2 sv = ps[e2], dv = pd[e2];
        s0 = (int)sv.x; s1 = (int)sv.y; d0 = (int)dv.x; d1 = (int)dv.y;
    } else if (mode == 1) {
        const int2* ps = (const int2*)ei;
        const int2* pd = (const int2*)((const int*)ei + E);
        int2 sv = ps[e2], dv = pd[e2];
        s0 = sv.x; s1 = sv.y; d0 = dv.x; d1 = dv.y;
    } else {
        const float2* ps = (const float2*)ei;
        const float2* pd = (const float2*)((const float*)ei + E);
        float2 sv = ps[e2], dv = pd[e2];
        s0 = (int)sv.x; s1 = (int)sv.y; d0 = (int)dv.x; d1 = (int)dv.y;
    }
    if ((unsigned)s0 >= NN) s0 = -1;
    if ((unsigned)s1 >= NN) s1 = -1;
    if ((unsigned)d0 >= NN) d0 = -1;
    if ((unsigned)d1 >= NN) d1 = -1;
    ((int4*)g_edge)[e2] = make_int4(s0, d0, s1, d1);
    if (d0 >= 0) atomicAdd(&g_deg[d0], 1.0f);
    if (d1 >= 0) atomicAdd(&g_deg[d1], 1.0f);
}

// K3: dinv = rsqrt(deg); xscaled[v] = x[v] * dinv (padded 6 -> 8)
__global__ void k_prep(const float* __restrict__ x, int n) {
    int v = blockIdx.x * blockDim.x + threadIdx.x;
    if (v >= n) return;
    float di = rsqrtf(g_deg[v]);
    g_deg[v] = di;
    const float* xv = x + (size_t)v * 6;
    float4* o = (float4*)(g_xs + (size_t)v * 8);
    o[0] = make_float4(xv[0] * di, xv[1] * di, xv[2] * di, xv[3] * di);
    o[1] = make_float4(xv[4] * di, xv[5] * di, 0.0f, 0.0f);
}

// K4: layer-1 scatter: agg1[d] += xscaled[s]
__global__ void k_scat1(int E) {
    int e = blockIdx.x * blockDim.x + threadIdx.x;
    if (e >= E) return;
    int2 ed = g_edge[e];
    if (ed.x < 0 || ed.y < 0) return;
    const float4* xs = (const float4*)(g_xs + (size_t)ed.x * 8);
    float4 v0 = __ldg(xs);
    float2 v1 = __ldg((const float2*)(xs + 1));
    float* ag = g_agg1 + (size_t)ed.y * 8;
    red_add_v4(ag,     v0.x, v0.y, v0.z, v0.w);
    red_add_v2(ag + 4, v1.x, v1.y);
}

// K5: a = di*(agg1 + xscaled); h = relu(a@W1+b1); p = h@W2; pscaled = p*di
__global__ void k_node(const float* __restrict__ W1, const float* __restrict__ b1,
                       const float* __restrict__ W2, int n) {
    __shared__ float sW1[6 * 64];
    __shared__ float sW2[64 * 8];
    __shared__ float sb1[64];
    for (int i = threadIdx.x; i < 6 * 64; i += blockDim.x) sW1[i] = W1[i];
    for (int i = threadIdx.x; i < 64 * 8; i += blockDim.x) sW2[i] = W2[i];
    for (int i = threadIdx.x; i < 64;     i += blockDim.x) sb1[i] = b1[i];
    __syncthreads();

    int v = blockIdx.x * blockDim.x + threadIdx.x;
    if (v >= n) return;

    float di = g_deg[v];
    const float4* ag = (const float4*)(g_agg1 + (size_t)v * 8);
    const float4* xs = (const float4*)(g_xs + (size_t)v * 8);
    float4 a0 = ag[0], a1 = ag[1];
    float4 x0 = xs[0], x1 = xs[1];

    float a[6];
    a[0] = di * (a0.x + x0.x);
    a[1] = di * (a0.y + x0.y);
    a[2] = di * (a0.z + x0.z);
    a[3] = di * (a0.w + x0.w);
    a[4] = di * (a1.x + x1.x);
    a[5] = di * (a1.y + x1.y);

    float p[8];
#pragma unroll
    for (int k = 0; k < 8; k++) p[k] = 0.0f;

#pragma unroll 8
    for (int j = 0; j < 64; j++) {
        float h = sb1[j];
#pragma unroll
        for (int i = 0; i < 6; i++) h = fmaf(a[i], sW1[i * 64 + j], h);
        h = fmaxf(h, 0.0f);
#pragma unroll
        for (int k = 0; k < 8; k++) p[k] = fmaf(h, sW2[j * 8 + k], p[k]);
    }

    float4 q0 = make_float4(p[0] * di, p[1] * di, p[2] * di, p[3] * di);
    float4 q1 = make_float4(p[4] * di, p[5] * di, p[6] * di, p[7] * di);
    float4* pr = (float4*)(g_p + (size_t)v * 8);
    float4* o  = (float4*)(g_out + (size_t)v * 8);
    pr[0] = q0; pr[1] = q1;
    o[0]  = q0; o[1]  = q1;   // self-loop seed (x di in k_final)
}

// K6: layer-2 scatter: g_out[d] += pscaled[s]
__global__ void k_scat2(int E) {
    int e = blockIdx.x * blockDim.x + threadIdx.x;
    if (e >= E) return;
    int2 ed = g_edge[e];
    if (ed.x < 0 || ed.y < 0) return;
    const float4* ps = (const float4*)(g_p + (size_t)ed.x * 8);
    float4 q0 = __ldg(ps);
    float4 q1 = __ldg(ps + 1);
    float* o = g_out + (size_t)ed.y * 8;
    red_add_v4(o,     q0.x, q0.y, q0.z, q0.w);
    red_add_v4(o + 4, q1.x, q1.y, q1.z, q1.w);
}

// K7: out[v] = di * accum[v] + b2
__global__ void k_final(const float* __restrict__ b2, float* __restrict__ out, int n) {
    int v = blockIdx.x * blockDim.x + threadIdx.x;
    if (v >= n) return;
    float di = g_deg[v];
    float4 bb0 = make_float4(b2[0], b2[1], b2[2], b2[3]);
    float4 bb1 = make_float4(b2[4], b2[5], b2[6], b2[7]);
    const float4* a = (const float4*)(g_out + (size_t)v * 8);
    float4 v0 = a[0], v1 = a[1];
    float4* o = (float4*)(out + (size_t)v * 8);
    o[0] = make_float4(fmaf(v0.x, di, bb0.x), fmaf(v0.y, di, bb0.y),
                       fmaf(v0.z, di, bb0.z), fmaf(v0.w, di, bb0.w));
    o[1] = make_float4(fmaf(v1.x, di, bb1.x), fmaf(v1.y, di, bb1.y),
                       fmaf(v1.z, di, bb1.z), fmaf(v1.w, di, bb1.w));
}

extern "C" void kernel_launch(void* const* d_in, const int* in_sizes, int n_in,
                              void* d_out, int out_size) {
    const void*  ei = d_in[1];
    const float* x  = (const float*)d_in[0];
    const float* W1 = (const float*)d_in[2];
    const float* b1 = (const float*)d_in[3];
    const float* W2 = (const float*)d_in[4];
    const float* b2 = (const float*)d_in[5];
    float*       out = (float*)d_out;

    const int N = NN;
    const int E = NE;

    k_init  <<<(N * 2 + 255) / 256, 256>>>(ei, N);       // N*2 float4 elems
    k_cvt   <<<(E / 2 + 255) / 256, 256>>>(ei, E);
    k_prep  <<<(N + 127) / 128, 128>>>(x, N);
    k_scat1 <<<(E + 255) / 256, 256>>>(E);
    k_node  <<<(N + 255) / 256, 256>>>(W1, b1, W2, N);
    k_scat2 <<<(E + 255) / 256, 256>>>(E);
    k_final <<<(N + 255) / 256, 256>>>(b2, out, N);
}